// round 1
// baseline (speedup 1.0000x reference)
#include <cuda_runtime.h>
#include <cstdint>

constexpr int NN   = 50000;
constexpr int INC  = 128;
constexpr int HIDC = 256;
constexpr int OUTC = 128;

__device__ float g_deg[NN];
__device__ float g_invdeg[NN];
__device__ float g_agg1[(size_t)NN * INC];
__device__ float g_h[(size_t)NN * HIDC];
__device__ float g_y[(size_t)NN * OUTC];
__device__ float g_agg2[(size_t)NN * OUTC];

__global__ void zero_kernel(float4* __restrict__ p, int n4) {
    int i = blockIdx.x * blockDim.x + threadIdx.x;
    int stride = gridDim.x * blockDim.x;
    for (; i < n4; i += stride)
        p[i] = make_float4(0.f, 0.f, 0.f, 0.f);
}

__global__ void deg_kernel(const int* __restrict__ dst, int E) {
    int i = blockIdx.x * blockDim.x + threadIdx.x;
    int stride = gridDim.x * blockDim.x;
    for (; i < E; i += stride)
        atomicAdd(&g_deg[dst[i]], 1.0f);
}

__global__ void invdeg_kernel() {
    int n = blockIdx.x * blockDim.x + threadIdx.x;
    if (n < NN)
        g_invdeg[n] = 1.0f / fmaxf(g_deg[n], 1.0f);
}

__global__ void scale_kernel() {
    int i = blockIdx.x * blockDim.x + threadIdx.x;
    int n4 = NN * (INC / 4);
    if (i < n4) {
        float s = g_invdeg[i >> 5];
        float4* p = reinterpret_cast<float4*>(g_agg1) + i;
        float4 v = *p;
        v.x *= s; v.y *= s; v.z *= s; v.w *= s;
        *p = v;
    }
}

// one warp per edge; float4 per lane; vector reduction into L2
__global__ void scatter128(const float* __restrict__ feat,
                           const int* __restrict__ esrc,
                           const int* __restrict__ edst,
                           float* __restrict__ outbuf, int E) {
    int gw = (blockIdx.x * blockDim.x + threadIdx.x) >> 5;
    if (gw >= E) return;
    int lane = threadIdx.x & 31;
    int s = __ldg(&esrc[gw]);
    int d = __ldg(&edst[gw]);
    const float4* sp = reinterpret_cast<const float4*>(feat) + (size_t)s * 32 + lane;
    float4 v = __ldg(sp);
    float4* dp = reinterpret_cast<float4*>(outbuf) + (size_t)d * 32 + lane;
    asm volatile("red.global.add.v4.f32 [%0], {%1, %2, %3, %4};"
                 :: "l"(dp), "f"(v.x), "f"(v.y), "f"(v.z), "f"(v.w)
                 : "memory");
}

template <bool HAS_A1, bool HAS_BIAS, bool RELU, bool HAS_ADD>
__global__ __launch_bounds__(256)
void gemm_kernel(const float* __restrict__ A0, const float* __restrict__ W0, int K0,
                 const float* __restrict__ A1, const float* __restrict__ W1, int K1,
                 const float* __restrict__ bias,
                 const float* __restrict__ addm,
                 const float* __restrict__ rowscale,
                 float* __restrict__ C, int M, int N) {
    constexpr int BM = 128, BN = 64, BK = 16;
    __shared__ float As[BK][BM + 4];
    __shared__ float Ws[BK][BN + 4];

    const int m0 = blockIdx.x * BM;
    const int n0 = blockIdx.y * BN;
    const int tid = threadIdx.x;
    const int tm = tid >> 4;
    const int tn = tid & 15;

    float acc[8][4];
#pragma unroll
    for (int i = 0; i < 8; i++)
#pragma unroll
        for (int j = 0; j < 4; j++) acc[i][j] = 0.f;

    const int Ktot = K0 + (HAS_A1 ? K1 : 0);

    for (int kt = 0; kt < Ktot; kt += BK) {
        const float* Ap;
        const float* Wp;
        int ld, kk0;
        if (!HAS_A1 || kt < K0) { Ap = A0; Wp = W0; ld = K0; kk0 = kt; }
        else                    { Ap = A1; Wp = W1; ld = K1; kk0 = kt - K0; }

#pragma unroll
        for (int it = 0; it < 2; it++) {
            int idx = it * 256 + tid;
            int row = idx >> 2;
            int c4  = idx & 3;
            int gm  = m0 + row;
            float4 v = make_float4(0.f, 0.f, 0.f, 0.f);
            if (gm < M)
                v = *reinterpret_cast<const float4*>(&Ap[(size_t)gm * ld + kk0 + c4 * 4]);
            As[c4 * 4 + 0][row] = v.x;
            As[c4 * 4 + 1][row] = v.y;
            As[c4 * 4 + 2][row] = v.z;
            As[c4 * 4 + 3][row] = v.w;
        }
        {
            int row = tid >> 2;
            int c4  = tid & 3;
            float4 v = *reinterpret_cast<const float4*>(
                &Wp[(size_t)(n0 + row) * ld + kk0 + c4 * 4]);
            Ws[c4 * 4 + 0][row] = v.x;
            Ws[c4 * 4 + 1][row] = v.y;
            Ws[c4 * 4 + 2][row] = v.z;
            Ws[c4 * 4 + 3][row] = v.w;
        }
        __syncthreads();

#pragma unroll
        for (int kk = 0; kk < BK; kk++) {
            float4 a0 = *reinterpret_cast<const float4*>(&As[kk][tm * 8]);
            float4 a1 = *reinterpret_cast<const float4*>(&As[kk][tm * 8 + 4]);
            float4 wv = *reinterpret_cast<const float4*>(&Ws[kk][tn * 4]);
            float a[8] = {a0.x, a0.y, a0.z, a0.w, a1.x, a1.y, a1.z, a1.w};
            float w[4] = {wv.x, wv.y, wv.z, wv.w};
#pragma unroll
            for (int i = 0; i < 8; i++)
#pragma unroll
                for (int j = 0; j < 4; j++)
                    acc[i][j] = fmaf(a[i], w[j], acc[i][j]);
        }
        __syncthreads();
    }

#pragma unroll
    for (int i = 0; i < 8; i++) {
        int m = m0 + tm * 8 + i;
        if (m >= M) continue;
        int n = n0 + tn * 4;
        float rs = HAS_ADD ? rowscale[m] : 0.f;
        float vals[4];
#pragma unroll
        for (int j = 0; j < 4; j++) {
            float v = acc[i][j];
            if (HAS_BIAS) v += bias[n + j];
            if (HAS_ADD)  v += addm[(size_t)m * N + n + j] * rs;
            if (RELU)     v = fmaxf(v, 0.f);
            vals[j] = v;
        }
        *reinterpret_cast<float4*>(&C[(size_t)m * N + n]) =
            make_float4(vals[0], vals[1], vals[2], vals[3]);
    }
}

extern "C" void kernel_launch(void* const* d_in, const int* in_sizes, int n_in,
                              void* d_out, int out_size) {
    const float* x    = (const float*)d_in[0];
    const int*   ei   = (const int*)d_in[1];
    const float* W1_l = (const float*)d_in[2];
    const float* b1_l = (const float*)d_in[3];
    const float* W1_r = (const float*)d_in[4];
    const float* W2_l = (const float*)d_in[5];
    const float* b2_l = (const float*)d_in[6];
    const float* W2_r = (const float*)d_in[7];
    float* out = (float*)d_out;

    const int E = in_sizes[1] / 2;
    const int* esrc = ei;
    const int* edst = ei + E;

    void *p_deg, *p_invdeg, *p_agg1, *p_h, *p_y, *p_agg2;
    cudaGetSymbolAddress(&p_deg,    g_deg);
    cudaGetSymbolAddress(&p_invdeg, g_invdeg);
    cudaGetSymbolAddress(&p_agg1,   g_agg1);
    cudaGetSymbolAddress(&p_h,      g_h);
    cudaGetSymbolAddress(&p_y,      g_y);
    cudaGetSymbolAddress(&p_agg2,   g_agg2);
    float* agg1   = (float*)p_agg1;
    float* hbuf   = (float*)p_h;
    float* ybuf   = (float*)p_y;
    float* agg2   = (float*)p_agg2;
    float* invdeg = (float*)p_invdeg;

    // 1) zero scratch
    int n4a = NN * INC / 4;
    zero_kernel<<<(n4a + 255) / 256, 256>>>((float4*)p_agg1, n4a);
    int n4b = NN * OUTC / 4;
    zero_kernel<<<(n4b + 255) / 256, 256>>>((float4*)p_agg2, n4b);
    int n4d = NN / 4;
    zero_kernel<<<(n4d + 255) / 256, 256>>>((float4*)p_deg, n4d);

    // 2) degrees
    deg_kernel<<<(E + 255) / 256, 256>>>(edst, E);

    // 3) scatter x -> agg1
    {
        long long threads = (long long)E * 32;
        int blocks = (int)((threads + 255) / 256);
        scatter128<<<blocks, 256>>>(x, esrc, edst, agg1, E);
    }

    // 4) invdeg; agg1 -> mean
    invdeg_kernel<<<(NN + 255) / 256, 256>>>();
    {
        int n4 = NN * INC / 4;
        scale_kernel<<<(n4 + 255) / 256, 256>>>();
    }

    // 5) h = relu(mean @ W1_l^T + x @ W1_r^T + b1)
    {
        dim3 grid((NN + 127) / 128, HIDC / 64);
        gemm_kernel<true, true, true, false><<<grid, 256>>>(
            agg1, W1_l, INC, x, W1_r, INC, b1_l, nullptr, nullptr,
            hbuf, NN, HIDC);
    }

    // 6) y = h @ W2_l^T   (transform before aggregation)
    {
        dim3 grid((NN + 127) / 128, OUTC / 64);
        gemm_kernel<false, false, false, false><<<grid, 256>>>(
            hbuf, W2_l, HIDC, nullptr, nullptr, 0, nullptr, nullptr, nullptr,
            ybuf, NN, OUTC);
    }

    // 7) scatter y -> agg2
    {
        long long threads = (long long)E * 32;
        int blocks = (int)((threads + 255) / 256);
        scatter128<<<blocks, 256>>>(ybuf, esrc, edst, agg2, E);
    }

    // 8) out = h @ W2_r^T + agg2 * invdeg + b2
    {
        dim3 grid((NN + 127) / 128, OUTC / 64);
        gemm_kernel<false, true, false, true><<<grid, 256>>>(
            hbuf, W2_r, HIDC, nullptr, nullptr, 0, b2_l, agg2, invdeg,
            out, NN, OUTC);
    }
}

// round 4
// speedup vs baseline: 1.5143x; 1.5143x over previous
#include <cuda_runtime.h>
#include <cuda_bf16.h>
#include <cstdint>

constexpr int NN   = 50000;
constexpr int INC  = 128;
constexpr int HIDC = 256;
constexpr int OUTC = 128;

__device__ float g_deg[NN];
__device__ float g_invdeg[NN];
__device__ float g_agg1[(size_t)NN * INC];    // neighbor-sum of x -> mean
__device__ float g_h[(size_t)NN * HIDC];      // layer-1 output (f32)
__device__ float g_c2[(size_t)NN * 256];      // [y | part] from layer-2 GEMM
__device__ float g_agg2[(size_t)NN * OUTC];   // neighbor-sum of y

// ---------------------------------------------------------------------------
// Simple kernels
// ---------------------------------------------------------------------------
__global__ void zero_kernel(float4* __restrict__ p, int n4) {
    int i = blockIdx.x * blockDim.x + threadIdx.x;
    int stride = gridDim.x * blockDim.x;
    for (; i < n4; i += stride)
        p[i] = make_float4(0.f, 0.f, 0.f, 0.f);
}

__global__ void deg_kernel(const int* __restrict__ dst, int E) {
    int i = blockIdx.x * blockDim.x + threadIdx.x;
    int stride = gridDim.x * blockDim.x;
    for (; i < E; i += stride)
        atomicAdd(&g_deg[dst[i]], 1.0f);
}

__global__ void invdeg_kernel() {
    int n = blockIdx.x * blockDim.x + threadIdx.x;
    if (n < NN)
        g_invdeg[n] = 1.0f / fmaxf(g_deg[n], 1.0f);
}

__global__ void scale_kernel() {
    int i = blockIdx.x * blockDim.x + threadIdx.x;
    int n4 = NN * (INC / 4);
    if (i < n4) {
        float s = g_invdeg[i >> 5];
        float4* p = reinterpret_cast<float4*>(g_agg1) + i;
        float4 v = *p;
        v.x *= s; v.y *= s; v.z *= s; v.w *= s;
        *p = v;
    }
}

// one warp per edge; float4 per lane; vector reduction into L2.
// feat rows have stride `fstride` floats (128 cols used); out rows 128 floats.
__global__ void scatter128(const float* __restrict__ feat, int fstride,
                           const int* __restrict__ esrc,
                           const int* __restrict__ edst,
                           float* __restrict__ outbuf, int E) {
    int gw = (blockIdx.x * blockDim.x + threadIdx.x) >> 5;
    if (gw >= E) return;
    int lane = threadIdx.x & 31;
    int s = __ldg(&esrc[gw]);
    int d = __ldg(&edst[gw]);
    const float4* sp = reinterpret_cast<const float4*>(feat + (size_t)s * fstride) + lane;
    float4 v = __ldg(sp);
    float4* dp = reinterpret_cast<float4*>(outbuf) + (size_t)d * 32 + lane;
    asm volatile("red.global.add.v4.f32 [%0], {%1, %2, %3, %4};"
                 :: "l"(dp), "f"(v.x), "f"(v.y), "f"(v.z), "f"(v.w)
                 : "memory");
}

// out = part + agg2*invdeg + b2   (part = g_c2 cols 128..255)
__global__ void final_add(const float* __restrict__ c2,
                          const float* __restrict__ agg2,
                          const float* __restrict__ invdeg,
                          const float* __restrict__ b2,
                          float* __restrict__ out) {
    int i = blockIdx.x * blockDim.x + threadIdx.x;
    int n4 = NN * (OUTC / 4);
    if (i >= n4) return;
    int m = i >> 5;
    int c4 = i & 31;
    float s = invdeg[m];
    float4 p = *reinterpret_cast<const float4*>(c2 + (size_t)m * 256 + 128 + c4 * 4);
    float4 a = reinterpret_cast<const float4*>(agg2)[i];
    float4 b = __ldg(reinterpret_cast<const float4*>(b2) + c4);
    float4 o;
    o.x = p.x + a.x * s + b.x;
    o.y = p.y + a.y * s + b.y;
    o.z = p.z + a.z * s + b.z;
    o.w = p.w + a.w * s + b.w;
    reinterpret_cast<float4*>(out)[i] = o;
}

// ---------------------------------------------------------------------------
// mma.sync m16n8k16 bf16 helper (baseline PTX, compiles at compute_100)
// ---------------------------------------------------------------------------
__device__ __forceinline__ void mma_bf16(float* d, const uint32_t* a,
                                         const uint32_t* b) {
    asm volatile(
        "mma.sync.aligned.m16n8k16.row.col.f32.bf16.bf16.f32 "
        "{%0,%1,%2,%3}, {%4,%5,%6,%7}, {%8,%9}, {%0,%1,%2,%3};"
        : "+f"(d[0]), "+f"(d[1]), "+f"(d[2]), "+f"(d[3])
        : "r"(a[0]), "r"(a[1]), "r"(a[2]), "r"(a[3]), "r"(b[0]), "r"(b[1]));
}

__device__ __forceinline__ void split2(float x, float y,
                                       uint32_t& hi, uint32_t& lo) {
    __nv_bfloat162 h = __floats2bfloat162_rn(x, y);
    __nv_bfloat162 l = __floats2bfloat162_rn(x - __bfloat162float(h.x),
                                             y - __bfloat162float(h.y));
    hi = *reinterpret_cast<uint32_t*>(&h);
    lo = *reinterpret_cast<uint32_t*>(&l);
}

// ---------------------------------------------------------------------------
// Split-bf16 HMMA GEMM: C[M,256] = act(A[M,256] @ B[256,256]^T (+bias))
// 3-term: hi*hi + hi*lo + lo*hi, fp32 accum -> ~fp32 accuracy.
// Block 128x128 (256 thr, 8 warps @ 32x64). K chunks of 32 floats.
// MODE 1: A = [agg1 | x] (two 128-col halves), B = [W1_l | W1_r], relu+bias.
// MODE 2: A = h (256),  B rows: n<128 -> W2_l, else W2_r. no act.
// ---------------------------------------------------------------------------
constexpr int PAD = 40;   // bf16 elems per smem row (32 data + 8 pad)

template <int MODE>
__global__ void __launch_bounds__(256, 2)
sage_gemm(const float* __restrict__ A0, const float* __restrict__ A1,
          const float* __restrict__ B0, const float* __restrict__ B1,
          const float* __restrict__ bias,
          float* __restrict__ C, int M) {
    __shared__ __nv_bfloat16 As_hi[128 * PAD];
    __shared__ __nv_bfloat16 As_lo[128 * PAD];
    __shared__ __nv_bfloat16 Bs_hi[128 * PAD];
    __shared__ __nv_bfloat16 Bs_lo[128 * PAD];

    const int tid = threadIdx.x;
    const int wid = tid >> 5, lane = tid & 31;
    const int wm = wid & 3, wn = wid >> 2;          // 4 x 2 warp grid
    const int m0 = blockIdx.x * 128, n0 = blockIdx.y * 128;

    float acc[2][8][4];
#pragma unroll
    for (int i = 0; i < 2; i++)
#pragma unroll
        for (int j = 0; j < 8; j++)
#pragma unroll
            for (int q = 0; q < 4; q++) acc[i][j][q] = 0.f;

    for (int ch = 0; ch < 8; ch++) {
        // ---- load A tile [128 x 32 f32], split to bf16 hi/lo ----
        const float* Ap;
        int ldA, ka;
        if (MODE == 1) {
            if (ch < 4) { Ap = A0; ka = ch * 32; }
            else        { Ap = A1; ka = (ch - 4) * 32; }
            ldA = 128;
        } else {
            Ap = A0; ldA = 256; ka = ch * 32;
        }
#pragma unroll
        for (int it = 0; it < 4; it++) {
            int idx = it * 256 + tid;
            int row = idx >> 3, f = idx & 7;        // 8 float4 per 32-f row
            int gm = m0 + row;
            float4 v = make_float4(0.f, 0.f, 0.f, 0.f);
            if (gm < M)
                v = *reinterpret_cast<const float4*>(Ap + (size_t)gm * ldA + ka + f * 4);
            uint32_t h01, l01, h23, l23;
            split2(v.x, v.y, h01, l01);
            split2(v.z, v.w, h23, l23);
            int off = row * PAD + f * 4;
            *reinterpret_cast<uint32_t*>(&As_hi[off])     = h01;
            *reinterpret_cast<uint32_t*>(&As_hi[off + 2]) = h23;
            *reinterpret_cast<uint32_t*>(&As_lo[off])     = l01;
            *reinterpret_cast<uint32_t*>(&As_lo[off + 2]) = l23;
        }
        // ---- load B tile [128 n-rows x 32 k], split ----
#pragma unroll
        for (int it = 0; it < 4; it++) {
            int idx = it * 256 + tid;
            int row = idx >> 3, f = idx & 7;
            int n = n0 + row;
            const float* bp;
            if (MODE == 1)
                bp = ((ch < 4) ? B0 : B1) + (size_t)n * 128 + ka;
            else
                bp = (n < 128) ? (B0 + (size_t)n * 256 + ka)
                               : (B1 + (size_t)(n - 128) * 256 + ka);
            float4 v = *reinterpret_cast<const float4*>(bp + f * 4);
            uint32_t h01, l01, h23, l23;
            split2(v.x, v.y, h01, l01);
            split2(v.z, v.w, h23, l23);
            int off = row * PAD + f * 4;
            *reinterpret_cast<uint32_t*>(&Bs_hi[off])     = h01;
            *reinterpret_cast<uint32_t*>(&Bs_hi[off + 2]) = h23;
            *reinterpret_cast<uint32_t*>(&Bs_lo[off])     = l01;
            *reinterpret_cast<uint32_t*>(&Bs_lo[off + 2]) = l23;
        }
        __syncthreads();

        // ---- compute: 2 k16 sub-steps ----
        const int r = lane >> 2, c = (lane & 3) * 2;
#pragma unroll
        for (int ks = 0; ks < 2; ks++) {
            const int k = ks * 16;
            uint32_t ahi[2][4], alo[2][4];
#pragma unroll
            for (int mt = 0; mt < 2; mt++) {
                int rr = wm * 32 + mt * 16 + r;
                ahi[mt][0] = *reinterpret_cast<const uint32_t*>(&As_hi[rr * PAD + k + c]);
                ahi[mt][1] = *reinterpret_cast<const uint32_t*>(&As_hi[(rr + 8) * PAD + k + c]);
                ahi[mt][2] = *reinterpret_cast<const uint32_t*>(&As_hi[rr * PAD + k + c + 8]);
                ahi[mt][3] = *reinterpret_cast<const uint32_t*>(&As_hi[(rr + 8) * PAD + k + c + 8]);
                alo[mt][0] = *reinterpret_cast<const uint32_t*>(&As_lo[rr * PAD + k + c]);
                alo[mt][1] = *reinterpret_cast<const uint32_t*>(&As_lo[(rr + 8) * PAD + k + c]);
                alo[mt][2] = *reinterpret_cast<const uint32_t*>(&As_lo[rr * PAD + k + c + 8]);
                alo[mt][3] = *reinterpret_cast<const uint32_t*>(&As_lo[(rr + 8) * PAD + k + c + 8]);
            }
#pragma unroll
            for (int nt = 0; nt < 8; nt++) {
                int nn = wn * 64 + nt * 8 + (lane >> 2);
                int kb = k + (lane & 3) * 2;
                uint32_t bhi[2], blo[2];
                bhi[0] = *reinterpret_cast<const uint32_t*>(&Bs_hi[nn * PAD + kb]);
                bhi[1] = *reinterpret_cast<const uint32_t*>(&Bs_hi[nn * PAD + kb + 8]);
                blo[0] = *reinterpret_cast<const uint32_t*>(&Bs_lo[nn * PAD + kb]);
                blo[1] = *reinterpret_cast<const uint32_t*>(&Bs_lo[nn * PAD + kb + 8]);
#pragma unroll
                for (int mt = 0; mt < 2; mt++) {
                    mma_bf16(acc[mt][nt], ahi[mt], bhi);
                    mma_bf16(acc[mt][nt], ahi[mt], blo);
                    mma_bf16(acc[mt][nt], alo[mt], bhi);
                }
            }
        }
        __syncthreads();
    }

    // ---- epilogue ----
#pragma unroll
    for (int mt = 0; mt < 2; mt++) {
#pragma unroll
        for (int nt = 0; nt < 8; nt++) {
            int m = m0 + wm * 32 + mt * 16 + (lane >> 2);
            int n = n0 + wn * 64 + nt * 8 + (lane & 3) * 2;
            float2 bz = make_float2(0.f, 0.f);
            if (MODE == 1)
                bz = *reinterpret_cast<const float2*>(bias + n);
            if (m < M) {
                float2 v;
                v.x = acc[mt][nt][0] + bz.x;
                v.y = acc[mt][nt][1] + bz.y;
                if (MODE == 1) { v.x = fmaxf(v.x, 0.f); v.y = fmaxf(v.y, 0.f); }
                *reinterpret_cast<float2*>(C + (size_t)m * 256 + n) = v;
            }
            if (m + 8 < M) {
                float2 v;
                v.x = acc[mt][nt][2] + bz.x;
                v.y = acc[mt][nt][3] + bz.y;
                if (MODE == 1) { v.x = fmaxf(v.x, 0.f); v.y = fmaxf(v.y, 0.f); }
                *reinterpret_cast<float2*>(C + (size_t)(m + 8) * 256 + n) = v;
            }
        }
    }
}

// ---------------------------------------------------------------------------
// Launch
// ---------------------------------------------------------------------------
extern "C" void kernel_launch(void* const* d_in, const int* in_sizes, int n_in,
                              void* d_out, int out_size) {
    const float* x    = (const float*)d_in[0];
    const int*   ei   = (const int*)d_in[1];
    const float* W1_l = (const float*)d_in[2];
    const float* b1_l = (const float*)d_in[3];
    const float* W1_r = (const float*)d_in[4];
    const float* W2_l = (const float*)d_in[5];
    const float* b2_l = (const float*)d_in[6];
    const float* W2_r = (const float*)d_in[7];
    float* out = (float*)d_out;

    const int E = in_sizes[1] / 2;
    const int* esrc = ei;
    const int* edst = ei + E;

    void *p_deg, *p_invdeg, *p_agg1, *p_h, *p_c2, *p_agg2;
    cudaGetSymbolAddress(&p_deg,    g_deg);
    cudaGetSymbolAddress(&p_invdeg, g_invdeg);
    cudaGetSymbolAddress(&p_agg1,   g_agg1);
    cudaGetSymbolAddress(&p_h,      g_h);
    cudaGetSymbolAddress(&p_c2,     g_c2);
    cudaGetSymbolAddress(&p_agg2,   g_agg2);
    float* agg1   = (float*)p_agg1;
    float* hbuf   = (float*)p_h;
    float* c2     = (float*)p_c2;
    float* agg2   = (float*)p_agg2;
    float* invdeg = (float*)p_invdeg;

    // 1) zero scratch
    int n4a = NN * INC / 4;
    zero_kernel<<<(n4a + 255) / 256, 256>>>((float4*)p_agg1, n4a);
    int n4b = NN * OUTC / 4;
    zero_kernel<<<(n4b + 255) / 256, 256>>>((float4*)p_agg2, n4b);
    int n4d = NN / 4;
    zero_kernel<<<(n4d + 255) / 256, 256>>>((float4*)p_deg, n4d);

    // 2) degrees
    deg_kernel<<<(E + 255) / 256, 256>>>(edst, E);

    // 3) scatter x -> agg1
    {
        long long threads = (long long)E * 32;
        int blocks = (int)((threads + 255) / 256);
        scatter128<<<blocks, 256>>>(x, 128, esrc, edst, agg1, E);
    }

    // 4) invdeg; agg1 -> mean
    invdeg_kernel<<<(NN + 255) / 256, 256>>>();
    {
        int n4 = NN * INC / 4;
        scale_kernel<<<(n4 + 255) / 256, 256>>>();
    }

    const dim3 grid((NN + 127) / 128, 2);

    // 5) h = relu([agg1 | x] @ [W1_l | W1_r]^T + b1)
    sage_gemm<1><<<grid, 256>>>(agg1, x, W1_l, W1_r, b1_l, hbuf, NN);

    // 6) [y | part] = h @ [W2_l ; W2_r]^T   (c2 = [NN][256], y = cols 0..127)
    sage_gemm<2><<<grid, 256>>>(hbuf, nullptr, W2_l, W2_r, nullptr, c2, NN);

    // 7) scatter y -> agg2   (y rows at stride 256)
    {
        long long threads = (long long)E * 32;
        int blocks = (int)((threads + 255) / 256);
        scatter128<<<blocks, 256>>>(c2, 256, esrc, edst, agg2, E);
    }

    // 8) out = part + agg2 * invdeg + b2
    {
        int n4 = NN * OUTC / 4;
        final_add<<<(n4 + 255) / 256, 256>>>(c2, agg2, invdeg, b2_l, out);
    }
}

// round 5
// speedup vs baseline: 1.8656x; 1.2320x over previous
#include <cuda_runtime.h>
#include <cuda_bf16.h>
#include <cstdint>

constexpr int NN   = 50000;
constexpr int INC  = 128;
constexpr int HIDC = 256;
constexpr int OUTC = 128;
constexpr int EMAX = 640000;

__device__ int   g_cnt[NN];          // histogram counts
__device__ int   g_fill[NN];         // placement cursors
__device__ int   g_rowptr[NN + 1];   // CSR row pointers (by dst)
__device__ int   g_col[EMAX];        // CSR column (src) indices
__device__ float g_agg1[(size_t)NN * INC];   // mean of x over in-neighbors
__device__ float g_h[(size_t)NN * HIDC];     // layer-1 output
__device__ float g_c2[(size_t)NN * 256];     // [y | part] from layer-2 GEMM

// ---------------------------------------------------------------------------
// CSR build
// ---------------------------------------------------------------------------
__global__ void zero_int2() {
    int i = blockIdx.x * blockDim.x + threadIdx.x;
    if (i < NN) { g_cnt[i] = 0; g_fill[i] = 0; }
}

__global__ void hist_kernel(const int* __restrict__ dst, int E) {
    int i = blockIdx.x * blockDim.x + threadIdx.x;
    int stride = gridDim.x * blockDim.x;
    for (; i < E; i += stride)
        atomicAdd(&g_cnt[dst[i]], 1);
}

// single-block exclusive scan over g_cnt[0..NN) -> g_rowptr
__global__ void __launch_bounds__(1024, 1) scan_kernel() {
    __shared__ int sums[1024];
    const int tid = threadIdx.x;
    const int CH = (NN + 1023) / 1024;   // 49
    const int base = tid * CH;

    int local = 0;
    for (int i = 0; i < CH; i++) {
        int idx = base + i;
        if (idx < NN) local += g_cnt[idx];
    }
    sums[tid] = local;
    __syncthreads();
    // Hillis-Steele inclusive scan
    for (int d = 1; d < 1024; d <<= 1) {
        int v = (tid >= d) ? sums[tid - d] : 0;
        __syncthreads();
        sums[tid] += v;
        __syncthreads();
    }
    int off = sums[tid] - local;   // exclusive prefix
    for (int i = 0; i < CH; i++) {
        int idx = base + i;
        if (idx < NN) {
            g_rowptr[idx] = off;
            off += g_cnt[idx];
        }
    }
    if (tid == 1023) g_rowptr[NN] = off;
}

__global__ void place_kernel(const int* __restrict__ src,
                             const int* __restrict__ dst, int E) {
    int i = blockIdx.x * blockDim.x + threadIdx.x;
    int stride = gridDim.x * blockDim.x;
    for (; i < E; i += stride) {
        int d = dst[i];
        int pos = atomicAdd(&g_fill[d], 1);
        g_col[g_rowptr[d] + pos] = src[i];
    }
}

// ---------------------------------------------------------------------------
// Gather-mean: one warp per node, 1 float4 per lane (128 cols).
// FIN=0: out[node*128+..] = mean(feat rows)                      (agg1)
// FIN=1: out = mean(feat rows) + c2[node*256+128+..] + b2        (final out)
// ---------------------------------------------------------------------------
template <int FIN>
__global__ void __launch_bounds__(256)
gather_mean(const float* __restrict__ feat, int fstride,
            const float* __restrict__ c2,
            const float* __restrict__ b2,
            float* __restrict__ out) {
    int node = (blockIdx.x * blockDim.x + threadIdx.x) >> 5;
    if (node >= NN) return;
    int lane = threadIdx.x & 31;
    int beg = __ldg(&g_rowptr[node]);
    int end = __ldg(&g_rowptr[node + 1]);

    float4 a0 = make_float4(0.f, 0.f, 0.f, 0.f);
    float4 a1 = make_float4(0.f, 0.f, 0.f, 0.f);
    int e = beg;
    for (; e + 1 < end; e += 2) {
        int s0 = __ldg(&g_col[e]);
        int s1 = __ldg(&g_col[e + 1]);
        float4 v0 = __ldg(reinterpret_cast<const float4*>(feat + (size_t)s0 * fstride) + lane);
        float4 v1 = __ldg(reinterpret_cast<const float4*>(feat + (size_t)s1 * fstride) + lane);
        a0.x += v0.x; a0.y += v0.y; a0.z += v0.z; a0.w += v0.w;
        a1.x += v1.x; a1.y += v1.y; a1.z += v1.z; a1.w += v1.w;
    }
    if (e < end) {
        int s0 = __ldg(&g_col[e]);
        float4 v0 = __ldg(reinterpret_cast<const float4*>(feat + (size_t)s0 * fstride) + lane);
        a0.x += v0.x; a0.y += v0.y; a0.z += v0.z; a0.w += v0.w;
    }
    float inv = 1.0f / (float)max(end - beg, 1);
    float4 r;
    r.x = (a0.x + a1.x) * inv;
    r.y = (a0.y + a1.y) * inv;
    r.z = (a0.z + a1.z) * inv;
    r.w = (a0.w + a1.w) * inv;

    if (FIN) {
        float4 p = *reinterpret_cast<const float4*>(c2 + (size_t)node * 256 + 128 + lane * 4);
        float4 b = __ldg(reinterpret_cast<const float4*>(b2) + lane);
        r.x += p.x + b.x;
        r.y += p.y + b.y;
        r.z += p.z + b.z;
        r.w += p.w + b.w;
    }
    *(reinterpret_cast<float4*>(out + (size_t)node * 128) + lane) = r;
}

// ---------------------------------------------------------------------------
// mma.sync m16n8k16 bf16 helper (baseline PTX, compiles at compute_100)
// ---------------------------------------------------------------------------
__device__ __forceinline__ void mma_bf16(float* d, const uint32_t* a,
                                         const uint32_t* b) {
    asm volatile(
        "mma.sync.aligned.m16n8k16.row.col.f32.bf16.bf16.f32 "
        "{%0,%1,%2,%3}, {%4,%5,%6,%7}, {%8,%9}, {%0,%1,%2,%3};"
        : "+f"(d[0]), "+f"(d[1]), "+f"(d[2]), "+f"(d[3])
        : "r"(a[0]), "r"(a[1]), "r"(a[2]), "r"(a[3]), "r"(b[0]), "r"(b[1]));
}

__device__ __forceinline__ void split2(float x, float y,
                                       uint32_t& hi, uint32_t& lo) {
    __nv_bfloat162 h = __floats2bfloat162_rn(x, y);
    __nv_bfloat162 l = __floats2bfloat162_rn(x - __bfloat162float(h.x),
                                             y - __bfloat162float(h.y));
    hi = *reinterpret_cast<uint32_t*>(&h);
    lo = *reinterpret_cast<uint32_t*>(&l);
}

// ---------------------------------------------------------------------------
// Split-bf16 HMMA GEMM: C[M,256] = act(A[M,256] @ B[256,256]^T (+bias))
// 3-term: hi*hi + hi*lo + lo*hi, fp32 accum -> ~fp32 accuracy.
// Block 128x128 (256 thr, 8 warps @ 32x64). K chunks of 32 floats.
// MODE 1: A = [agg1 | x] (two 128-col halves), B = [W1_l | W1_r], relu+bias.
// MODE 2: A = h (256),  B rows: n<128 -> W2_l, else W2_r. no act.
// ---------------------------------------------------------------------------
constexpr int PAD = 40;

template <int MODE>
__global__ void __launch_bounds__(256, 2)
sage_gemm(const float* __restrict__ A0, const float* __restrict__ A1,
          const float* __restrict__ B0, const float* __restrict__ B1,
          const float* __restrict__ bias,
          float* __restrict__ C, int M) {
    __shared__ __nv_bfloat16 As_hi[128 * PAD];
    __shared__ __nv_bfloat16 As_lo[128 * PAD];
    __shared__ __nv_bfloat16 Bs_hi[128 * PAD];
    __shared__ __nv_bfloat16 Bs_lo[128 * PAD];

    const int tid = threadIdx.x;
    const int wid = tid >> 5, lane = tid & 31;
    const int wm = wid & 3, wn = wid >> 2;
    const int m0 = blockIdx.x * 128, n0 = blockIdx.y * 128;

    float acc[2][8][4];
#pragma unroll
    for (int i = 0; i < 2; i++)
#pragma unroll
        for (int j = 0; j < 8; j++)
#pragma unroll
            for (int q = 0; q < 4; q++) acc[i][j][q] = 0.f;

    for (int ch = 0; ch < 8; ch++) {
        const float* Ap;
        int ldA, ka;
        if (MODE == 1) {
            if (ch < 4) { Ap = A0; ka = ch * 32; }
            else        { Ap = A1; ka = (ch - 4) * 32; }
            ldA = 128;
        } else {
            Ap = A0; ldA = 256; ka = ch * 32;
        }
#pragma unroll
        for (int it = 0; it < 4; it++) {
            int idx = it * 256 + tid;
            int row = idx >> 3, f = idx & 7;
            int gm = m0 + row;
            float4 v = make_float4(0.f, 0.f, 0.f, 0.f);
            if (gm < M)
                v = *reinterpret_cast<const float4*>(Ap + (size_t)gm * ldA + ka + f * 4);
            uint32_t h01, l01, h23, l23;
            split2(v.x, v.y, h01, l01);
            split2(v.z, v.w, h23, l23);
            int off = row * PAD + f * 4;
            *reinterpret_cast<uint32_t*>(&As_hi[off])     = h01;
            *reinterpret_cast<uint32_t*>(&As_hi[off + 2]) = h23;
            *reinterpret_cast<uint32_t*>(&As_lo[off])     = l01;
            *reinterpret_cast<uint32_t*>(&As_lo[off + 2]) = l23;
        }
#pragma unroll
        for (int it = 0; it < 4; it++) {
            int idx = it * 256 + tid;
            int row = idx >> 3, f = idx & 7;
            int n = n0 + row;
            const float* bp;
            if (MODE == 1)
                bp = ((ch < 4) ? B0 : B1) + (size_t)n * 128 + ka;
            else
                bp = (n < 128) ? (B0 + (size_t)n * 256 + ka)
                               : (B1 + (size_t)(n - 128) * 256 + ka);
            float4 v = *reinterpret_cast<const float4*>(bp + f * 4);
            uint32_t h01, l01, h23, l23;
            split2(v.x, v.y, h01, l01);
            split2(v.z, v.w, h23, l23);
            int off = row * PAD + f * 4;
            *reinterpret_cast<uint32_t*>(&Bs_hi[off])     = h01;
            *reinterpret_cast<uint32_t*>(&Bs_hi[off + 2]) = h23;
            *reinterpret_cast<uint32_t*>(&Bs_lo[off])     = l01;
            *reinterpret_cast<uint32_t*>(&Bs_lo[off + 2]) = l23;
        }
        __syncthreads();

        const int r = lane >> 2, c = (lane & 3) * 2;
#pragma unroll
        for (int ks = 0; ks < 2; ks++) {
            const int k = ks * 16;
            uint32_t ahi[2][4], alo[2][4];
#pragma unroll
            for (int mt = 0; mt < 2; mt++) {
                int rr = wm * 32 + mt * 16 + r;
                ahi[mt][0] = *reinterpret_cast<const uint32_t*>(&As_hi[rr * PAD + k + c]);
                ahi[mt][1] = *reinterpret_cast<const uint32_t*>(&As_hi[(rr + 8) * PAD + k + c]);
                ahi[mt][2] = *reinterpret_cast<const uint32_t*>(&As_hi[rr * PAD + k + c + 8]);
                ahi[mt][3] = *reinterpret_cast<const uint32_t*>(&As_hi[(rr + 8) * PAD + k + c + 8]);
                alo[mt][0] = *reinterpret_cast<const uint32_t*>(&As_lo[rr * PAD + k + c]);
                alo[mt][1] = *reinterpret_cast<const uint32_t*>(&As_lo[(rr + 8) * PAD + k + c]);
                alo[mt][2] = *reinterpret_cast<const uint32_t*>(&As_lo[rr * PAD + k + c + 8]);
                alo[mt][3] = *reinterpret_cast<const uint32_t*>(&As_lo[(rr + 8) * PAD + k + c + 8]);
            }
#pragma unroll
            for (int nt = 0; nt < 8; nt++) {
                int nn = wn * 64 + nt * 8 + (lane >> 2);
                int kb = k + (lane & 3) * 2;
                uint32_t bhi[2], blo[2];
                bhi[0] = *reinterpret_cast<const uint32_t*>(&Bs_hi[nn * PAD + kb]);
                bhi[1] = *reinterpret_cast<const uint32_t*>(&Bs_hi[nn * PAD + kb + 8]);
                blo[0] = *reinterpret_cast<const uint32_t*>(&Bs_lo[nn * PAD + kb]);
                blo[1] = *reinterpret_cast<const uint32_t*>(&Bs_lo[nn * PAD + kb + 8]);
#pragma unroll
                for (int mt = 0; mt < 2; mt++) {
                    mma_bf16(acc[mt][nt], ahi[mt], bhi);
                    mma_bf16(acc[mt][nt], ahi[mt], blo);
                    mma_bf16(acc[mt][nt], alo[mt], bhi);
                }
            }
        }
        __syncthreads();
    }

#pragma unroll
    for (int mt = 0; mt < 2; mt++) {
#pragma unroll
        for (int nt = 0; nt < 8; nt++) {
            int m = m0 + wm * 32 + mt * 16 + (lane >> 2);
            int n = n0 + wn * 64 + nt * 8 + (lane & 3) * 2;
            float2 bz = make_float2(0.f, 0.f);
            if (MODE == 1)
                bz = *reinterpret_cast<const float2*>(bias + n);
            if (m < M) {
                float2 v;
                v.x = acc[mt][nt][0] + bz.x;
                v.y = acc[mt][nt][1] + bz.y;
                if (MODE == 1) { v.x = fmaxf(v.x, 0.f); v.y = fmaxf(v.y, 0.f); }
                *reinterpret_cast<float2*>(C + (size_t)m * 256 + n) = v;
            }
            if (m + 8 < M) {
                float2 v;
                v.x = acc[mt][nt][2] + bz.x;
                v.y = acc[mt][nt][3] + bz.y;
                if (MODE == 1) { v.x = fmaxf(v.x, 0.f); v.y = fmaxf(v.y, 0.f); }
                *reinterpret_cast<float2*>(C + (size_t)(m + 8) * 256 + n) = v;
            }
        }
    }
}

// ---------------------------------------------------------------------------
// Launch
// ---------------------------------------------------------------------------
extern "C" void kernel_launch(void* const* d_in, const int* in_sizes, int n_in,
                              void* d_out, int out_size) {
    const float* x    = (const float*)d_in[0];
    const int*   ei   = (const int*)d_in[1];
    const float* W1_l = (const float*)d_in[2];
    const float* b1_l = (const float*)d_in[3];
    const float* W1_r = (const float*)d_in[4];
    const float* W2_l = (const float*)d_in[5];
    const float* b2_l = (const float*)d_in[6];
    const float* W2_r = (const float*)d_in[7];
    float* out = (float*)d_out;

    const int E = in_sizes[1] / 2;
    const int* esrc = ei;
    const int* edst = ei + E;

    void *p_agg1, *p_h, *p_c2;
    cudaGetSymbolAddress(&p_agg1, g_agg1);
    cudaGetSymbolAddress(&p_h,    g_h);
    cudaGetSymbolAddress(&p_c2,   g_c2);
    float* agg1 = (float*)p_agg1;
    float* hbuf = (float*)p_h;
    float* c2   = (float*)p_c2;

    // ---- CSR build (by dst) ----
    zero_int2<<<(NN + 255) / 256, 256>>>();
    hist_kernel<<<(E + 511) / 512, 256>>>(edst, E);
    scan_kernel<<<1, 1024>>>();
    place_kernel<<<(E + 511) / 512, 256>>>(esrc, edst, E);

    // ---- agg1 = mean of x over in-neighbors ----
    {
        int blocks = (NN * 32 + 255) / 256;
        gather_mean<0><<<blocks, 256>>>(x, 128, nullptr, nullptr, agg1);
    }

    const dim3 grid((NN + 127) / 128, 2);

    // ---- h = relu([agg1 | x] @ [W1_l | W1_r]^T + b1) ----
    sage_gemm<1><<<grid, 256>>>(agg1, x, W1_l, W1_r, b1_l, hbuf, NN);

    // ---- [y | part] = h @ [W2_l ; W2_r]^T ----
    sage_gemm<2><<<grid, 256>>>(hbuf, nullptr, W2_l, W2_r, nullptr, c2, NN);

    // ---- out = mean of y over in-neighbors + part + b2 ----
    {
        int blocks = (NN * 32 + 255) / 256;
        gather_mean<1><<<blocks, 256>>>(c2, 256, c2, b2_l, out);
    }
}